// round 3
// baseline (speedup 1.0000x reference)
#include <cuda_runtime.h>
#include <math.h>

#define NN    256
#define BATCH 16
#define WID   64
#define MD    16
#define HSZ   (BATCH*WID*NN*NN)

typedef unsigned long long u64;

// ---------------- f32x2 packed helpers ----------------
__device__ __forceinline__ u64 pack2(float lo, float hi) {
    u64 r; asm("mov.b64 %0,{%1,%2};" : "=l"(r) : "f"(lo), "f"(hi)); return r;
}
__device__ __forceinline__ void unpack2(u64 v, float &lo, float &hi) {
    asm("mov.b64 {%0,%1},%2;" : "=f"(lo), "=f"(hi) : "l"(v));
}
__device__ __forceinline__ void ffma2(u64 &d, u64 a, u64 b) {
    asm("fma.rn.f32x2 %0,%1,%2,%0;" : "+l"(d) : "l"(a), "l"(b));
}

// ---------------- scratch ----------------
__device__ __align__(16) float g_h0[HSZ];
__device__ __align__(16) float g_h1[HSZ];
__device__ __align__(16) float g_fy [BATCH*WID*NN*MD*2];
__device__ __align__(16) float g_fxy[BATCH*WID*MD*MD*2];
__device__ __align__(16) float g_ymix[BATCH*WID*MD*MD*2];
__device__ __align__(16) float g_gx [BATCH*WID*NN*MD*2];
__device__ __align__(16) float2 g_tab[NN];

__device__ __forceinline__ float* hbuf(int s) { return s ? g_h1 : g_h0; }

__global__ void init_tab_kernel() {
    int m = threadIdx.x;
    double a = (2.0 * 3.14159265358979323846 * (double)m) / 256.0;
    g_tab[m] = make_float2((float)cos(a), (float)sin(a));
}

// ---------------- shared Fy stage (forward y-DFT of a full output row) ----------------
#define SR 260

__device__ __forceinline__ void fy_stage(const float* __restrict__ res,
                                         const u64* __restrict__ tbl,
                                         int b, int xx, int tid) {
    int o = tid >> 2, q = tid & 3;
    const float* rp = res + o * SR;
    const u64* tq = tbl + q * 4;
    u64 a0 = 0, a1 = 0, a2 = 0, a3 = 0;
#pragma unroll 4
    for (int y = 0; y < 128; y++) {
        float lo = rp[y], hi = rp[y + 128];
        float sp = lo + hi, sm = lo - hi;
        u64 psp = pack2(sp, sp);
        u64 psm = pack2(sm, sm);
        const u64* tr = tq + y * 17;
        ffma2(a0, psp, tr[0]);
        ffma2(a1, psm, tr[1]);
        ffma2(a2, psp, tr[2]);
        ffma2(a3, psm, tr[3]);
    }
    float* fp = g_fy + (((size_t)(b * 64 + o) * 256 + xx) << 5) + q * 8;
    reinterpret_cast<ulonglong2*>(fp)[0] = make_ulonglong2(a0, a1);
    reinterpret_cast<ulonglong2*>(fp)[1] = make_ulonglong2(a2, a3);
}

__device__ __forceinline__ void build_tbl(u64* tbl, int tid) {
    for (int idx = tid; idx < 2048; idx += 256) {
        int y = idx >> 4, k = idx & 15;
        float2 e = g_tab[(y * k) & 255];
        tbl[y * 17 + k] = pack2(e.x, -e.y);
    }
}

// ---------------- lift + Fy ----------------
#define F0_TBL 16640
#define F0_XS  (F0_TBL + 4352)
#define F0_WS  (F0_XS + 768)
#define F0_BS  (F0_WS + 192)
#define F0_FLOATS (F0_BS + 64)
#define F0_SMEM (F0_FLOATS * 4)

__global__ __launch_bounds__(256, 2) void fc0_fy(const float* __restrict__ x,
                                                 const float* __restrict__ w,
                                                 const float* __restrict__ bias) {
    extern __shared__ float smf[];
    int tid = threadIdx.x;
    int b = blockIdx.x >> 8, xx = blockIdx.x & 255;
    float* xs = smf + F0_XS;
    float* ws = smf + F0_WS;
    float* bs = smf + F0_BS;
    u64* tbl = reinterpret_cast<u64*>(smf + F0_TBL);

    for (int idx = tid; idx < 768; idx += 256) {
        int c = idx >> 8, y = idx & 255;
        xs[idx] = x[((size_t)(b * 3 + c) * 256 + xx) * 256 + y];
    }
    if (tid < 192) ws[tid] = w[tid];
    if (tid < 64)  bs[tid] = bias[tid];
    build_tbl(tbl, tid);
    __syncthreads();

    int o = tid >> 2, yc = (tid & 3) * 64;
    float w0 = ws[o * 3], w1 = ws[o * 3 + 1], w2v = ws[o * 3 + 2], bb = bs[o];
#pragma unroll 8
    for (int j = 0; j < 64; j++) {
        int y = yc + j;
        smf[o * SR + y] = fmaf(w0, xs[y], fmaf(w1, xs[256 + y], fmaf(w2v, xs[512 + y], bb)));
    }
    __syncthreads();

#pragma unroll
    for (int j = 0; j < 16; j++) {
        int slot = tid + j * 256;
        int oo = slot >> 6, y4 = (slot & 63) * 4;
        float4 v = *reinterpret_cast<const float4*>(&smf[oo * SR + y4]);
        *reinterpret_cast<float4*>(g_h0 + ((size_t)(b * 64 + oo) << 16) + xx * 256 + y4) = v;
    }
    fy_stage(smf, tbl, b, xx, tid);
}

// ---------------- stage 2a: x-forward DFT ----------------
__global__ __launch_bounds__(256) void dftx_fwd() {
    __shared__ float2 Fs[NN * MD];
    __shared__ float2 tb[NN];
    int tid = threadIdx.x;
    int bc  = blockIdx.x;
    const float4* src = reinterpret_cast<const float4*>(g_fy + (size_t)bc * NN * 32);
    float4* fd = reinterpret_cast<float4*>(Fs);
#pragma unroll
    for (int j = 0; j < 8; j++) fd[tid + j * 256] = src[tid + j * 256];
    tb[tid] = g_tab[tid];
    __syncthreads();
    int k1 = tid >> 4, k2 = tid & 15;
    float re = 0.f, im = 0.f;
    int m = 0;
#pragma unroll 8
    for (int x = 0; x < NN; x++) {
        float2 F = Fs[x * 16 + k2];
        float2 e = tb[m];
        m = (m + k1) & 255;
        re = fmaf(F.x, e.x, re); re = fmaf(F.y, e.y, re);
        im = fmaf(F.y, e.x, im); im = fmaf(-F.x, e.y, im);
    }
    g_fxy[(size_t)bc * 512 + tid * 2    ] = re;
    g_fxy[(size_t)bc * 512 + tid * 2 + 1] = im;
}

// ---------------- stage 2b: per-mode channel mix (restructured) ----------------
__global__ __launch_bounds__(256) void mode_mix(const float* __restrict__ sw) {
    __shared__ float WsR[WID * WID];
    __shared__ float WsI[WID * WID];
    __shared__ float2 Xs[BATCH * WID];
    int tid  = threadIdx.x;
    int mode = blockIdx.x;
    for (int idx = tid; idx < WID * WID; idx += 256) {
        const float* p = sw + ((size_t)idx * 256 + mode) * 2;
        WsR[idx] = p[0];
        WsI[idx] = p[1];
    }
    for (int idx = tid; idx < BATCH * WID; idx += 256) {
        const float* p = g_fxy + ((size_t)idx * 256 + mode) * 2;
        Xs[idx] = make_float2(p[0], p[1]);
    }
    __syncthreads();
    int o = tid & 63, bg = tid >> 6;
    const float sc = 1.0f / 65536.0f;
#pragma unroll
    for (int t = 0; t < 4; t++) {
        int b = bg * 4 + t;
        float aR = 0.f, aI = 0.f;
#pragma unroll 8
        for (int i = 0; i < 64; i++) {
            float2 X = Xs[b * 64 + i];
            float wr = WsR[i * 64 + o], wi = WsI[i * 64 + o];
            aR = fmaf(X.x, wr, aR); aR = fmaf(-X.y, wi, aR);
            aI = fmaf(X.x, wi, aI); aI = fmaf( X.y, wr, aI);
        }
        float* p = g_ymix + ((size_t)(b * 64 + o) * 256 + mode) * 2;
        p[0] = aR * sc;
        p[1] = aI * sc;
    }
}

// ---------------- stage 2c: x-inverse DFT ----------------
__global__ __launch_bounds__(256) void dftx_inv() {
    __shared__ float2 Ys[256];
    __shared__ float2 tb[NN];
    int tid = threadIdx.x;
    int bo  = blockIdx.x;
    Ys[tid] = reinterpret_cast<const float2*>(g_ymix)[(size_t)bo * 256 + tid];
    tb[tid] = g_tab[tid];
    __syncthreads();
    int x = tid;
    float2 acc[16];
#pragma unroll
    for (int k2 = 0; k2 < 16; k2++) acc[k2] = make_float2(0.f, 0.f);
    int m = 0;
#pragma unroll
    for (int k1 = 0; k1 < 16; k1++) {
        float2 e = tb[m];
        m = (m + x) & 255;
#pragma unroll
        for (int k2 = 0; k2 < 16; k2++) {
            float2 Yv = Ys[k1 * 16 + k2];
            acc[k2].x = fmaf(Yv.x, e.x, acc[k2].x); acc[k2].x = fmaf(-Yv.y, e.y, acc[k2].x);
            acc[k2].y = fmaf(Yv.x, e.y, acc[k2].y); acc[k2].y = fmaf( Yv.y, e.x, acc[k2].y);
        }
    }
    float* dst = g_gx + ((size_t)bo * 256 + x) * 32;
#pragma unroll
    for (int k2 = 0; k2 < 16; k2++) { dst[2 * k2] = acc[k2].x; dst[2 * k2 + 1] = acc[k2].y; }
}

// ---------------- stage 3 (mega-fused, pack-free f32x2) ----------------
// smem float offsets
#define OFF_CW2  16384                  // u64[64*64] dup weights   (8192 floats)
#define OFF_TBL  24576                  // u64[128*17] fy table     (4352 floats)
#define OFF_TBLP 28928                  // u64[128*16*2] inv-y pairs(8192 floats)
#define OFF_GR   37120                  // u64[16*64] dup g real    (2048 floats)
#define OFF_GI   39168                  // u64[16*64] dup g imag    (2048 floats)
#define OFF_CB   41216
#define OFF_HW   41280
#define OFF_HB   41344
#define CONV_FLOATS 41352
#define CONV_SMEM   (CONV_FLOATS * 4)

__global__ __launch_bounds__(256, 1) void conv_fused(int src, int dst,
                                                     const float* __restrict__ cw,
                                                     const float* __restrict__ cb,
                                                     int hasSpec, int doFy, int doHead,
                                                     const float* __restrict__ hw,
                                                     const float* __restrict__ hb,
                                                     float* __restrict__ out) {
    extern __shared__ float smf[];
    u64*  cws2 = reinterpret_cast<u64*>(smf + OFF_CW2);
    u64*  tbl  = reinterpret_cast<u64*>(smf + OFF_TBL);
    u64*  tblP = reinterpret_cast<u64*>(smf + OFF_TBLP);
    u64*  gdR  = reinterpret_cast<u64*>(smf + OFF_GR);
    u64*  gdI  = reinterpret_cast<u64*>(smf + OFF_GI);
    float* cbs = smf + OFF_CB;

    const float* __restrict__ hin = hbuf(src);
    float* __restrict__ hout = hbuf(dst);
    int tid = threadIdx.x;
    int b = blockIdx.x >> 8;
    int xx = blockIdx.x & 255;

    // ---- staging ----
    const float* hbase = hin + ((size_t)b * 64 * 256 + xx) * 256;
#pragma unroll
    for (int j = 0; j < 16; j++) {
        int slot = tid + j * 256;
        int i = slot >> 6, c4 = slot & 63;
        float4 v = *reinterpret_cast<const float4*>(hbase + (size_t)i * 65536 + c4 * 4);
        *reinterpret_cast<float4*>(&smf[i * 256 + c4 * 4]) = v;
    }
    // weights: duplicated pairs, conflict-free smem writes (o fast)
    for (int idx = tid; idx < 4096; idx += 256) {
        int o = idx & 63, i = idx >> 6;
        float wv = cw[o * 64 + i];
        cws2[i * 64 + o] = pack2(wv, wv);
    }
    build_tbl(tbl, tid);
    if (doFy | hasSpec) {
        // inverse-y twiddle pairs: tblP[(yp*16+k2)*2] = (cos_lo,cos_hi), +1 = (-sin_lo,-sin_hi)
        for (int idx = tid; idx < 2048; idx += 256) {
            int yp = idx >> 4, k2 = idx & 15;
            float2 e0 = g_tab[(k2 * (2 * yp))     & 255];
            float2 e1 = g_tab[(k2 * (2 * yp + 1)) & 255];
            tblP[(yp * 16 + k2) * 2    ] = pack2(e0.x, e1.x);
            tblP[(yp * 16 + k2) * 2 + 1] = pack2(-e0.y, -e1.y);
        }
    }
    if (hasSpec) {
        for (int idx = tid; idx < 1024; idx += 256) {
            int k2 = idx >> 6, o = idx & 63;
            const float* p = g_gx + (((size_t)(b * 64 + o) * 256 + xx) << 5) + 2 * k2;
            float d = (k2 > 0) ? 2.f : 1.f;
            gdR[k2 * 64 + o] = pack2(d * p[0], d * p[0]);
            gdI[k2 * 64 + o] = pack2(d * p[1], d * p[1]);
        }
    }
    if (tid < 64) cbs[tid] = cb[tid];
    if (doHead) {
        if (tid < 64) smf[OFF_HW + tid] = hw[tid];
        if (tid == 0) smf[OFF_HB] = hb[0];
    }
    __syncthreads();

    int o0 = (tid & 7) * 8;
    int y0 = (tid >> 3) * 8;
    u64 acc[4][8];     // [y-pair][o]
#pragma unroll
    for (int a = 0; a < 4; a++)
#pragma unroll
        for (int c = 0; c < 8; c++) acc[a][c] = 0ull;

    // ---- spectral inverse-y (pack-free) ----
    if (hasSpec) {
        int ypg0 = y0 >> 1;
#pragma unroll 1
        for (int k2 = 0; k2 < 16; k2++) {
            const u64* grp = gdR + k2 * 64 + o0;
            const u64* gip = gdI + k2 * 64 + o0;
            ulonglong2 r0 = reinterpret_cast<const ulonglong2*>(grp)[0];
            ulonglong2 r1 = reinterpret_cast<const ulonglong2*>(grp)[1];
            ulonglong2 r2 = reinterpret_cast<const ulonglong2*>(grp)[2];
            ulonglong2 r3 = reinterpret_cast<const ulonglong2*>(grp)[3];
            ulonglong2 i0 = reinterpret_cast<const ulonglong2*>(gip)[0];
            ulonglong2 i1 = reinterpret_cast<const ulonglong2*>(gip)[1];
            ulonglong2 i2 = reinterpret_cast<const ulonglong2*>(gip)[2];
            ulonglong2 i3 = reinterpret_cast<const ulonglong2*>(gip)[3];
            u64 gr[8] = {r0.x, r0.y, r1.x, r1.y, r2.x, r2.y, r3.x, r3.y};
            u64 gi[8] = {i0.x, i0.y, i1.x, i1.y, i2.x, i2.y, i3.x, i3.y};
#pragma unroll
            for (int yp = 0; yp < 4; yp++) {
                ulonglong2 tw = *reinterpret_cast<const ulonglong2*>(
                    tblP + ((ypg0 + yp) * 16 + k2) * 2);
#pragma unroll
                for (int oo = 0; oo < 8; oo++) {
                    ffma2(acc[yp][oo], gr[oo], tw.x);
                    ffma2(acc[yp][oo], gi[oo], tw.y);
                }
            }
        }
    }

    // ---- conv1x1 mainloop: 6 LDS.128 + 32 ffma2 per i ----
#pragma unroll 4
    for (int i = 0; i < 64; i++) {
        const u64* wp = cws2 + i * 64 + o0;
        ulonglong2 w0 = reinterpret_cast<const ulonglong2*>(wp)[0];
        ulonglong2 w1 = reinterpret_cast<const ulonglong2*>(wp)[1];
        ulonglong2 w2 = reinterpret_cast<const ulonglong2*>(wp)[2];
        ulonglong2 w3 = reinterpret_cast<const ulonglong2*>(wp)[3];
        const u64* hp = reinterpret_cast<const u64*>(smf + i * 256 + y0);
        ulonglong2 h0 = reinterpret_cast<const ulonglong2*>(hp)[0];
        ulonglong2 h1 = reinterpret_cast<const ulonglong2*>(hp)[1];
        u64 wd[8] = {w0.x, w0.y, w1.x, w1.y, w2.x, w2.y, w3.x, w3.y};
        u64 hpair[4] = {h0.x, h0.y, h1.x, h1.y};
#pragma unroll
        for (int yp = 0; yp < 4; yp++)
#pragma unroll
            for (int oo = 0; oo < 8; oo++)
                ffma2(acc[yp][oo], wd[oo], hpair[yp]);
    }

    // ---- bias + exact GELU + writeback ----
    __syncthreads();   // all smem reads done; res may overwrite
    int writeRes = doFy | doHead;
#pragma unroll
    for (int oo = 0; oo < 8; oo++) {
        int o = o0 + oo;
        float bias = cbs[o];
        float v[8];
#pragma unroll
        for (int yp = 0; yp < 4; yp++) {
            float a, bb; unpack2(acc[yp][oo], a, bb);
            float p = a + bias, q = bb + bias;
            v[2 * yp]     = 0.5f * p * (1.0f + erff(p * 0.70710678118654752f));
            v[2 * yp + 1] = 0.5f * q * (1.0f + erff(q * 0.70710678118654752f));
        }
        if (writeRes) {
            *reinterpret_cast<float4*>(&smf[o * SR + y0    ]) = make_float4(v[0], v[1], v[2], v[3]);
            *reinterpret_cast<float4*>(&smf[o * SR + y0 + 4]) = make_float4(v[4], v[5], v[6], v[7]);
        }
        if (!doHead) {
            float4* dp = reinterpret_cast<float4*>(hout + ((size_t)(b * 64 + o) << 16) + xx * 256 + y0);
            dp[0] = make_float4(v[0], v[1], v[2], v[3]);
            dp[1] = make_float4(v[4], v[5], v[6], v[7]);
        }
    }

    if (doFy) {
        __syncthreads();
        fy_stage(smf, tbl, b, xx, tid);
    }
    if (doHead) {
        __syncthreads();
        const float* hwS = smf + OFF_HW;
        float a = smf[OFF_HB];
        int y = tid;
#pragma unroll 16
        for (int f = 0; f < 64; f++) a = fmaf(smf[f * SR + y], hwS[f], a);
        out[(size_t)b * 65536 + xx * 256 + y] = a;
    }
}

// ---------------- launch ----------------
extern "C" void kernel_launch(void* const* d_in, const int* in_sizes, int n_in,
                              void* d_out, int out_size) {
    const float* x     = (const float*)d_in[0];
    const float* fc0_w = (const float*)d_in[1];
    const float* fc0_b = (const float*)d_in[2];
    const float* sw[4] = {(const float*)d_in[3], (const float*)d_in[4],
                          (const float*)d_in[5], (const float*)d_in[6]};
    const float* cw[4] = {(const float*)d_in[7], (const float*)d_in[9],
                          (const float*)d_in[11], (const float*)d_in[13]};
    const float* cb[4] = {(const float*)d_in[8], (const float*)d_in[10],
                          (const float*)d_in[12], (const float*)d_in[14]};
    const float* fc1_w = (const float*)d_in[15];
    const float* fc1_b = (const float*)d_in[16];
    const float* fc2_w = (const float*)d_in[17];
    const float* fc2_b = (const float*)d_in[18];
    float* out = (float*)d_out;

    cudaFuncSetAttribute(conv_fused, cudaFuncAttributeMaxDynamicSharedMemorySize, CONV_SMEM);
    cudaFuncSetAttribute(fc0_fy,     cudaFuncAttributeMaxDynamicSharedMemorySize, F0_SMEM);

    init_tab_kernel<<<1, 256>>>();
    fc0_fy<<<4096, 256, F0_SMEM>>>(x, fc0_w, fc0_b);

    int src = 0;
    for (int l = 0; l < 4; l++) {
        dftx_fwd<<<1024, 256>>>();
        mode_mix<<<256, 256>>>(sw[l]);
        dftx_inv<<<1024, 256>>>();
        int doFy = (l < 3) ? 1 : 0;
        conv_fused<<<4096, 256, CONV_SMEM>>>(src, 1 - src, cw[l], cb[l],
                                             1, doFy, 0, nullptr, nullptr, nullptr);
        src = 1 - src;
    }
    conv_fused<<<4096, 256, CONV_SMEM>>>(src, src, fc1_w, fc1_b,
                                         0, 0, 1, fc2_w, fc2_b, out);
}

// round 4
// speedup vs baseline: 2.0313x; 2.0313x over previous
#include <cuda_runtime.h>
#include <math.h>

#define NN    256
#define BATCH 16
#define WID   64
#define MD    16
#define HSZ   (BATCH*WID*NN*NN)

typedef unsigned long long u64;

// ---------------- f32x2 packed helpers ----------------
__device__ __forceinline__ u64 pack2(float lo, float hi) {
    u64 r; asm("mov.b64 %0,{%1,%2};" : "=l"(r) : "f"(lo), "f"(hi)); return r;
}
__device__ __forceinline__ void unpack2(u64 v, float &lo, float &hi) {
    asm("mov.b64 {%0,%1},%2;" : "=f"(lo), "=f"(hi) : "l"(v));
}
__device__ __forceinline__ void ffma2(u64 &d, u64 a, u64 b) {
    asm("fma.rn.f32x2 %0,%1,%2,%0;" : "+l"(d) : "l"(a), "l"(b));
}

// ---------------- scratch ----------------
__device__ __align__(16) float g_h0[HSZ];
__device__ __align__(16) float g_h1[HSZ];
__device__ __align__(16) float g_fy [BATCH*WID*NN*MD*2];
__device__ __align__(16) float g_fxy[BATCH*WID*MD*MD*2];
__device__ __align__(16) float g_ymix[BATCH*WID*MD*MD*2];
__device__ __align__(16) float g_gx [BATCH*WID*NN*MD*2];
__device__ __align__(16) float2 g_tab[NN];

__device__ __forceinline__ float* hbuf(int s) { return s ? g_h1 : g_h0; }

__global__ void init_tab_kernel() {
    int m = threadIdx.x;
    double a = (2.0 * 3.14159265358979323846 * (double)m) / 256.0;
    g_tab[m] = make_float2((float)cos(a), (float)sin(a));
}

// ---------------- shared Fy stage ----------------
#define SR 260

__device__ __forceinline__ void fy_stage(const float* __restrict__ res,
                                         const u64* __restrict__ tbl,
                                         int b, int xx, int tid) {
    int o = tid >> 2, q = tid & 3;
    const float* rp = res + o * SR;
    const u64* tq = tbl + q * 4;
    u64 a0 = 0, a1 = 0, a2 = 0, a3 = 0;
#pragma unroll 4
    for (int y = 0; y < 128; y++) {
        float lo = rp[y], hi = rp[y + 128];
        float sp = lo + hi, sm = lo - hi;
        u64 psp = pack2(sp, sp);
        u64 psm = pack2(sm, sm);
        const u64* tr = tq + y * 17;
        ffma2(a0, psp, tr[0]);
        ffma2(a1, psm, tr[1]);
        ffma2(a2, psp, tr[2]);
        ffma2(a3, psm, tr[3]);
    }
    float* fp = g_fy + (((size_t)(b * 64 + o) * 256 + xx) << 5) + q * 8;
    reinterpret_cast<ulonglong2*>(fp)[0] = make_ulonglong2(a0, a1);
    reinterpret_cast<ulonglong2*>(fp)[1] = make_ulonglong2(a2, a3);
}

__device__ __forceinline__ void build_tbl(u64* tbl, int tid) {
    for (int idx = tid; idx < 2048; idx += 256) {
        int y = idx >> 4, k = idx & 15;
        float2 e = g_tab[(y * k) & 255];
        tbl[y * 17 + k] = pack2(e.x, -e.y);
    }
}

// ---------------- lift + Fy ----------------
#define F0_TBL 16640
#define F0_XS  (F0_TBL + 4352)
#define F0_WS  (F0_XS + 768)
#define F0_BS  (F0_WS + 192)
#define F0_FLOATS (F0_BS + 64)
#define F0_SMEM (F0_FLOATS * 4)

__global__ __launch_bounds__(256, 2) void fc0_fy(const float* __restrict__ x,
                                                 const float* __restrict__ w,
                                                 const float* __restrict__ bias) {
    extern __shared__ float smf[];
    int tid = threadIdx.x;
    int b = blockIdx.x >> 8, xx = blockIdx.x & 255;
    float* xs = smf + F0_XS;
    float* ws = smf + F0_WS;
    float* bs = smf + F0_BS;
    u64* tbl = reinterpret_cast<u64*>(smf + F0_TBL);

    for (int idx = tid; idx < 768; idx += 256) {
        int c = idx >> 8, y = idx & 255;
        xs[idx] = x[((size_t)(b * 3 + c) * 256 + xx) * 256 + y];
    }
    if (tid < 192) ws[tid] = w[tid];
    if (tid < 64)  bs[tid] = bias[tid];
    build_tbl(tbl, tid);
    __syncthreads();

    int o = tid >> 2, yc = (tid & 3) * 64;
    float w0 = ws[o * 3], w1 = ws[o * 3 + 1], w2v = ws[o * 3 + 2], bb = bs[o];
#pragma unroll 8
    for (int j = 0; j < 64; j++) {
        int y = yc + j;
        smf[o * SR + y] = fmaf(w0, xs[y], fmaf(w1, xs[256 + y], fmaf(w2v, xs[512 + y], bb)));
    }
    __syncthreads();

#pragma unroll
    for (int j = 0; j < 16; j++) {
        int slot = tid + j * 256;
        int oo = slot >> 6, y4 = (slot & 63) * 4;
        float4 v = *reinterpret_cast<const float4*>(&smf[oo * SR + y4]);
        *reinterpret_cast<float4*>(g_h0 + ((size_t)(b * 64 + oo) << 16) + xx * 256 + y4) = v;
    }
    fy_stage(smf, tbl, b, xx, tid);
}

// ---------------- stage 2a: x-forward DFT (k2-pair vectorized, 128 thr/block) ----------------
__global__ __launch_bounds__(128) void dftx_fwd() {
    __shared__ float2 Fs[NN * MD];   // [x][k2]
    __shared__ float2 tb[NN];
    int t = threadIdx.x;             // 0..127
    int bc = blockIdx.x;
    const float4* src = reinterpret_cast<const float4*>(g_fy + (size_t)bc * NN * 32);
    float4* fd = reinterpret_cast<float4*>(Fs);
#pragma unroll
    for (int j = 0; j < 16; j++) fd[t + j * 128] = src[t + j * 128];
    tb[t] = g_tab[t];
    tb[t + 128] = g_tab[t + 128];
    __syncthreads();
    int k1 = t >> 3;                 // 0..15
    int k2p = t & 7;                 // pair of k2: (2*k2p, 2*k2p+1)
    float re0 = 0.f, im0 = 0.f, re1 = 0.f, im1 = 0.f;
    int m = 0;
#pragma unroll 8
    for (int x = 0; x < NN; x++) {
        float4 F = *reinterpret_cast<const float4*>(&Fs[x * 16 + k2p * 2]);
        float2 e = tb[m];
        m = (m + k1) & 255;
        re0 = fmaf(F.x, e.x, re0); re0 = fmaf(F.y, e.y, re0);
        im0 = fmaf(F.y, e.x, im0); im0 = fmaf(-F.x, e.y, im0);
        re1 = fmaf(F.z, e.x, re1); re1 = fmaf(F.w, e.y, re1);
        im1 = fmaf(F.w, e.x, im1); im1 = fmaf(-F.z, e.y, im1);
    }
    *reinterpret_cast<float4*>(g_fxy + (size_t)bc * 512 + k1 * 32 + k2p * 4) =
        make_float4(re0, im0, re1, im1);
}

// ---------------- stage 2b: per-mode channel mix ----------------
__global__ __launch_bounds__(256) void mode_mix(const float* __restrict__ sw) {
    __shared__ float WsR[WID * WID];
    __shared__ float WsI[WID * WID];
    __shared__ float2 Xs[BATCH * WID];
    int tid  = threadIdx.x;
    int mode = blockIdx.x;
    for (int idx = tid; idx < WID * WID; idx += 256) {
        const float* p = sw + ((size_t)idx * 256 + mode) * 2;
        WsR[idx] = p[0];
        WsI[idx] = p[1];
    }
    for (int idx = tid; idx < BATCH * WID; idx += 256) {
        const float* p = g_fxy + ((size_t)idx * 256 + mode) * 2;
        Xs[idx] = make_float2(p[0], p[1]);
    }
    __syncthreads();
    int o = tid & 63, bg = tid >> 6;
    const float sc = 1.0f / 65536.0f;
#pragma unroll
    for (int t = 0; t < 4; t++) {
        int b = bg * 4 + t;
        float aR = 0.f, aI = 0.f;
#pragma unroll 8
        for (int i = 0; i < 64; i++) {
            float2 X = Xs[b * 64 + i];
            float wr = WsR[i * 64 + o], wi = WsI[i * 64 + o];
            aR = fmaf(X.x, wr, aR); aR = fmaf(-X.y, wi, aR);
            aI = fmaf(X.x, wi, aI); aI = fmaf( X.y, wr, aI);
        }
        float* p = g_ymix + ((size_t)(b * 64 + o) * 256 + mode) * 2;
        p[0] = aR * sc;
        p[1] = aI * sc;
    }
}

// ---------------- stage 2c: x-inverse DFT ----------------
__global__ __launch_bounds__(256) void dftx_inv() {
    __shared__ float2 Ys[256];
    __shared__ float2 tb[NN];
    int tid = threadIdx.x;
    int bo  = blockIdx.x;
    Ys[tid] = reinterpret_cast<const float2*>(g_ymix)[(size_t)bo * 256 + tid];
    tb[tid] = g_tab[tid];
    __syncthreads();
    int x = tid;
    float2 acc[16];
#pragma unroll
    for (int k2 = 0; k2 < 16; k2++) acc[k2] = make_float2(0.f, 0.f);
    int m = 0;
#pragma unroll
    for (int k1 = 0; k1 < 16; k1++) {
        float2 e = tb[m];
        m = (m + x) & 255;
#pragma unroll
        for (int k2 = 0; k2 < 16; k2++) {
            float2 Yv = Ys[k1 * 16 + k2];
            acc[k2].x = fmaf(Yv.x, e.x, acc[k2].x); acc[k2].x = fmaf(-Yv.y, e.y, acc[k2].x);
            acc[k2].y = fmaf(Yv.x, e.y, acc[k2].y); acc[k2].y = fmaf( Yv.y, e.x, acc[k2].y);
        }
    }
    float* dst = g_gx + ((size_t)bo * 256 + x) * 32;
#pragma unroll
    for (int k2 = 0; k2 < 16; k2++) { dst[2 * k2] = acc[k2].x; dst[2 * k2 + 1] = acc[k2].y; }
}

// ---------------- stage 3 (mega-fused; R2 layout: o-pair accumulators) ----------------
#define OFF_CW  16384
#define OFF_TBL 20736
#define OFF_GR  25088
#define OFF_GI  26176
#define OFF_CB  27264
#define OFF_HW  27328
#define OFF_HB  27392
#define CONV_FLOATS 27400
#define CONV_SMEM   (CONV_FLOATS * 4)

__global__ __launch_bounds__(256, 2) void conv_fused(int src, int dst,
                                                     const float* __restrict__ cw,
                                                     const float* __restrict__ cb,
                                                     int hasSpec, int doFy, int doHead,
                                                     const float* __restrict__ hw,
                                                     const float* __restrict__ hb,
                                                     float* __restrict__ out) {
    extern __shared__ float smf[];
    float* cws = smf + OFF_CW;
    u64*  tbl  = reinterpret_cast<u64*>(smf + OFF_TBL);
    float* gsRe = smf + OFF_GR;
    float* gsIm = smf + OFF_GI;
    float* cbs  = smf + OFF_CB;

    const float* __restrict__ hin = hbuf(src);
    float* __restrict__ hout = hbuf(dst);
    int tid = threadIdx.x;
    int b = blockIdx.x >> 8;
    int xx = blockIdx.x & 255;

    // ---- staging ----
    const float* hbase = hin + ((size_t)b * 64 * 256 + xx) * 256;
#pragma unroll
    for (int j = 0; j < 16; j++) {
        int slot = tid + j * 256;
        int i = slot >> 6, c4 = slot & 63;
        float4 v = *reinterpret_cast<const float4*>(hbase + (size_t)i * 65536 + c4 * 4);
        *reinterpret_cast<float4*>(&smf[i * 256 + c4 * 4]) = v;
    }
    for (int idx = tid; idx < 4096; idx += 256) {
        int o = idx >> 6, i = idx & 63;
        cws[i * 68 + o] = cw[idx];           // transpose: cw[o][i] -> cws[i][o]
    }
    build_tbl(tbl, tid);
    if (hasSpec) {
        for (int idx = tid; idx < 1024; idx += 256) {
            int k2 = idx >> 6, o = idx & 63;
            const float* p = g_gx + (((size_t)(b * 64 + o) * 256 + xx) << 5) + 2 * k2;
            float d = (k2 > 0) ? 2.f : 1.f;
            gsRe[k2 * 68 + o] = d * p[0];
            gsIm[k2 * 68 + o] = d * p[1];
        }
    }
    if (tid < 64) cbs[tid] = cb[tid];
    if (doHead) {
        if (tid < 64) smf[OFF_HW + tid] = hw[tid];
        if (tid == 0) smf[OFF_HB] = hb[0];
    }
    __syncthreads();

    int o0 = (tid & 7) * 8;
    int y0 = (tid >> 3) * 8;
    u64 acc[4][8];   // [o-pair][y]
#pragma unroll
    for (int a = 0; a < 4; a++)
#pragma unroll
        for (int c = 0; c < 8; c++) acc[a][c] = 0ull;

    // ---- spectral inverse-y (o-pairs loaded directly as u64) ----
    if (hasSpec) {
        int ylo = y0 & 127;
        bool up = (y0 >= 128);
#pragma unroll 1
        for (int k2 = 0; k2 < 16; k2++) {
            float sg = (up && (k2 & 1)) ? -1.f : 1.f;
            const ulonglong2* grp = reinterpret_cast<const ulonglong2*>(gsRe + k2 * 68 + o0);
            const ulonglong2* gip = reinterpret_cast<const ulonglong2*>(gsIm + k2 * 68 + o0);
            ulonglong2 rA = grp[0], rB = grp[1];
            ulonglong2 iA = gip[0], iB = gip[1];
            u64 gr2[4] = {rA.x, rA.y, rB.x, rB.y};
            u64 gi2[4] = {iA.x, iA.y, iB.x, iB.y};
            const u64* tp = tbl + ylo * 17 + k2;
#pragma unroll
            for (int yy = 0; yy < 8; yy++) {
                float c, s; unpack2(tp[yy * 17], c, s);   // c=cos, s=-sin
                u64 pc = pack2(sg * c, sg * c);
                u64 ps = pack2(sg * s, sg * s);
                ffma2(acc[0][yy], gr2[0], pc); ffma2(acc[0][yy], gi2[0], ps);
                ffma2(acc[1][yy], gr2[1], pc); ffma2(acc[1][yy], gi2[1], ps);
                ffma2(acc[2][yy], gr2[2], pc); ffma2(acc[2][yy], gi2[2], ps);
                ffma2(acc[3][yy], gr2[3], pc); ffma2(acc[3][yy], gi2[3], ps);
            }
        }
    }

    // ---- conv1x1 mainloop ----
#pragma unroll 4
    for (int i = 0; i < 64; i++) {
        ulonglong2 wA = *reinterpret_cast<const ulonglong2*>(cws + i * 68 + o0);
        ulonglong2 wB = *reinterpret_cast<const ulonglong2*>(cws + i * 68 + o0 + 4);
        float4 hA = *reinterpret_cast<const float4*>(smf + i * 256 + y0);
        float4 hB = *reinterpret_cast<const float4*>(smf + i * 256 + y0 + 4);
        u64 w2[4] = {wA.x, wA.y, wB.x, wB.y};
        float hv[8] = {hA.x, hA.y, hA.z, hA.w, hB.x, hB.y, hB.z, hB.w};
#pragma unroll
        for (int yy = 0; yy < 8; yy++) {
            u64 h2 = pack2(hv[yy], hv[yy]);
            ffma2(acc[0][yy], w2[0], h2);
            ffma2(acc[1][yy], w2[1], h2);
            ffma2(acc[2][yy], w2[2], h2);
            ffma2(acc[3][yy], w2[3], h2);
        }
    }

    // ---- bias + exact GELU, write hout and/or res smem ----
    __syncthreads();
    int writeRes = doFy | doHead;
#pragma unroll
    for (int oop = 0; oop < 4; oop++) {
        int oE = o0 + oop * 2, oO = oE + 1;
        float bE = cbs[oE], bO = cbs[oO];
        float vE[8], vO[8];
#pragma unroll
        for (int yy = 0; yy < 8; yy++) {
            float a, bb; unpack2(acc[oop][yy], a, bb);
            float v = a + bE;
            vE[yy] = 0.5f * v * (1.0f + erff(v * 0.70710678118654752f));
            float w = bb + bO;
            vO[yy] = 0.5f * w * (1.0f + erff(w * 0.70710678118654752f));
        }
        if (writeRes) {
            *reinterpret_cast<float4*>(&smf[oE * SR + y0    ]) = make_float4(vE[0], vE[1], vE[2], vE[3]);
            *reinterpret_cast<float4*>(&smf[oE * SR + y0 + 4]) = make_float4(vE[4], vE[5], vE[6], vE[7]);
            *reinterpret_cast<float4*>(&smf[oO * SR + y0    ]) = make_float4(vO[0], vO[1], vO[2], vO[3]);
            *reinterpret_cast<float4*>(&smf[oO * SR + y0 + 4]) = make_float4(vO[4], vO[5], vO[6], vO[7]);
        }
        if (!doHead) {
            float4* dE = reinterpret_cast<float4*>(hout + ((size_t)(b * 64 + oE) << 16) + xx * 256 + y0);
            dE[0] = make_float4(vE[0], vE[1], vE[2], vE[3]);
            dE[1] = make_float4(vE[4], vE[5], vE[6], vE[7]);
            float4* dO = reinterpret_cast<float4*>(hout + ((size_t)(b * 64 + oO) << 16) + xx * 256 + y0);
            dO[0] = make_float4(vO[0], vO[1], vO[2], vO[3]);
            dO[1] = make_float4(vO[4], vO[5], vO[6], vO[7]);
        }
    }

    if (doFy) {
        __syncthreads();
        fy_stage(smf, tbl, b, xx, tid);
    }
    if (doHead) {
        __syncthreads();
        const float* hwS = smf + OFF_HW;
        float a = smf[OFF_HB];
        int y = tid;
#pragma unroll 16
        for (int f = 0; f < 64; f++) a = fmaf(smf[f * SR + y], hwS[f], a);
        out[(size_t)b * 65536 + xx * 256 + y] = a;
    }
}

// ---------------- launch ----------------
extern "C" void kernel_launch(void* const* d_in, const int* in_sizes, int n_in,
                              void* d_out, int out_size) {
    const float* x     = (const float*)d_in[0];
    const float* fc0_w = (const float*)d_in[1];
    const float* fc0_b = (const float*)d_in[2];
    const float* sw[4] = {(const float*)d_in[3], (const float*)d_in[4],
                          (const float*)d_in[5], (const float*)d_in[6]};
    const float* cw[4] = {(const float*)d_in[7], (const float*)d_in[9],
                          (const float*)d_in[11], (const float*)d_in[13]};
    const float* cb[4] = {(const float*)d_in[8], (const float*)d_in[10],
                          (const float*)d_in[12], (const float*)d_in[14]};
    const float* fc1_w = (const float*)d_in[15];
    const float* fc1_b = (const float*)d_in[16];
    const float* fc2_w = (const float*)d_in[17];
    const float* fc2_b = (const float*)d_in[18];
    float* out = (float*)d_out;

    cudaFuncSetAttribute(conv_fused, cudaFuncAttributeMaxDynamicSharedMemorySize, CONV_SMEM);
    cudaFuncSetAttribute(fc0_fy,     cudaFuncAttributeMaxDynamicSharedMemorySize, F0_SMEM);

    init_tab_kernel<<<1, 256>>>();
    fc0_fy<<<4096, 256, F0_SMEM>>>(x, fc0_w, fc0_b);

    int src = 0;
    for (int l = 0; l < 4; l++) {
        dftx_fwd<<<1024, 128>>>();
        mode_mix<<<256, 256>>>(sw[l]);
        dftx_inv<<<1024, 256>>>();
        int doFy = (l < 3) ? 1 : 0;
        conv_fused<<<4096, 256, CONV_SMEM>>>(src, 1 - src, cw[l], cb[l],
                                             1, doFy, 0, nullptr, nullptr, nullptr);
        src = 1 - src;
    }
    conv_fused<<<4096, 256, CONV_SMEM>>>(src, src, fc1_w, fc1_b,
                                         0, 0, 1, fc2_w, fc2_b, out);
}

// round 5
// speedup vs baseline: 2.2184x; 1.0921x over previous
#include <cuda_runtime.h>
#include <math.h>

#define NN    256
#define BATCH 16
#define WID   64
#define MD    16
#define HSZ   (BATCH*WID*NN*NN)

typedef unsigned long long u64;

// ---------------- f32x2 packed helpers ----------------
__device__ __forceinline__ u64 pack2(float lo, float hi) {
    u64 r; asm("mov.b64 %0,{%1,%2};" : "=l"(r) : "f"(lo), "f"(hi)); return r;
}
__device__ __forceinline__ void unpack2(u64 v, float &lo, float &hi) {
    asm("mov.b64 {%0,%1},%2;" : "=f"(lo), "=f"(hi) : "l"(v));
}
__device__ __forceinline__ void ffma2(u64 &d, u64 a, u64 b) {
    asm("fma.rn.f32x2 %0,%1,%2,%0;" : "+l"(d) : "l"(a), "l"(b));
}
__device__ __forceinline__ u64 addf2(u64 a, u64 b) {
    u64 r; asm("add.rn.f32x2 %0,%1,%2;" : "=l"(r) : "l"(a), "l"(b)); return r;
}
__device__ __forceinline__ u64 mulf2(u64 a, u64 b) {
    u64 r; asm("mul.rn.f32x2 %0,%1,%2;" : "=l"(r) : "l"(a), "l"(b)); return r;
}

// ---------------- scratch ----------------
__device__ __align__(16) float g_h0[HSZ];
__device__ __align__(16) float g_h1[HSZ];
__device__ __align__(16) float g_fy [BATCH*WID*NN*MD*2];
__device__ __align__(16) float g_fxy[BATCH*WID*MD*MD*2];
__device__ __align__(16) float g_ymix[BATCH*WID*MD*MD*2];
__device__ __align__(16) float g_gx [BATCH*WID*NN*MD*2];
__device__ __align__(16) float g_swt[4*256*4096*2];   // transposed spectral weights
__device__ __align__(16) float2 g_tab[NN];

__device__ __forceinline__ float* hbuf(int s) { return s ? g_h1 : g_h0; }

__global__ void init_tab_kernel() {
    int m = threadIdx.x;
    double a = (2.0 * 3.14159265358979323846 * (double)m) / 256.0;
    g_tab[m] = make_float2((float)cos(a), (float)sin(a));
}

// ---------------- sw transpose: sw[io][mode]{re,im} -> swt[l][mode][io]{re,im} ----------------
__global__ __launch_bounds__(256) void sw_transpose(const float* __restrict__ s0,
                                                    const float* __restrict__ s1,
                                                    const float* __restrict__ s2,
                                                    const float* __restrict__ s3) {
    __shared__ float2 tile[32][65];
    int tid = threadIdx.x;
    int l   = blockIdx.x >> 9;
    int iot = (blockIdx.x >> 3) & 63;
    int mt  = blockIdx.x & 7;
    const float* sw = (l == 0) ? s0 : (l == 1) ? s1 : (l == 2) ? s2 : s3;
    int io0 = iot * 64, m0 = mt * 32;
    int c = tid & 31, r = tid >> 5;
#pragma unroll
    for (int rr = r; rr < 64; rr += 8)
        tile[c][rr] = reinterpret_cast<const float2*>(sw)[(size_t)(io0 + rr) * 256 + m0 + c];
    __syncthreads();
    int c2 = tid & 63, mr = tid >> 6;
    float2* dst = reinterpret_cast<float2*>(g_swt);
#pragma unroll
    for (int mm = mr; mm < 32; mm += 4)
        dst[((size_t)(l * 256 + m0 + mm) * 4096) + io0 + c2] = tile[mm][c2];
}

// ---------------- shared Fy stage ----------------
#define SR 260

__device__ __forceinline__ void fy_stage(const float* __restrict__ res,
                                         const u64* __restrict__ tbl,
                                         int b, int xx, int tid) {
    int o = tid >> 2, q = tid & 3;
    const float* rp = res + o * SR;
    const u64* tq = tbl + q * 4;
    u64 a0 = 0, a1 = 0, a2 = 0, a3 = 0;
#pragma unroll 4
    for (int y = 0; y < 128; y++) {
        float lo = rp[y], hi = rp[y + 128];
        float sp = lo + hi, sm = lo - hi;
        u64 psp = pack2(sp, sp);
        u64 psm = pack2(sm, sm);
        const u64* tr = tq + y * 16;
        ulonglong2 t01 = *reinterpret_cast<const ulonglong2*>(tr);
        ulonglong2 t23 = *reinterpret_cast<const ulonglong2*>(tr + 2);
        ffma2(a0, psp, t01.x);
        ffma2(a1, psm, t01.y);
        ffma2(a2, psp, t23.x);
        ffma2(a3, psm, t23.y);
    }
    float* fp = g_fy + (((size_t)(b * 64 + o) * 256 + xx) << 5) + q * 8;
    reinterpret_cast<ulonglong2*>(fp)[0] = make_ulonglong2(a0, a1);
    reinterpret_cast<ulonglong2*>(fp)[1] = make_ulonglong2(a2, a3);
}

// tbl[y*16 + k] = (cos(2pi k y/256), -sin(...)) for y in [0,128)
__device__ __forceinline__ void build_tbl(u64* tbl, int tid) {
    for (int idx = tid; idx < 2048; idx += 256) {
        int y = idx >> 4, k = idx & 15;
        float2 e = g_tab[(y * k) & 255];
        tbl[idx] = pack2(e.x, -e.y);
    }
}

// ---------------- lift + Fy ----------------
#define F0_TBL 16640
#define F0_XS  (F0_TBL + 4096)
#define F0_WS  (F0_XS + 768)
#define F0_BS  (F0_WS + 192)
#define F0_FLOATS (F0_BS + 64)
#define F0_SMEM (F0_FLOATS * 4)

__global__ __launch_bounds__(256, 2) void fc0_fy(const float* __restrict__ x,
                                                 const float* __restrict__ w,
                                                 const float* __restrict__ bias) {
    extern __shared__ float smf[];
    int tid = threadIdx.x;
    int b = blockIdx.x >> 8, xx = blockIdx.x & 255;
    float* xs = smf + F0_XS;
    float* ws = smf + F0_WS;
    float* bs = smf + F0_BS;
    u64* tbl = reinterpret_cast<u64*>(smf + F0_TBL);

    for (int idx = tid; idx < 768; idx += 256) {
        int c = idx >> 8, y = idx & 255;
        xs[idx] = x[((size_t)(b * 3 + c) * 256 + xx) * 256 + y];
    }
    if (tid < 192) ws[tid] = w[tid];
    if (tid < 64)  bs[tid] = bias[tid];
    build_tbl(tbl, tid);
    __syncthreads();

    int o = tid >> 2, yc = (tid & 3) * 64;
    float w0 = ws[o * 3], w1 = ws[o * 3 + 1], w2v = ws[o * 3 + 2], bb = bs[o];
#pragma unroll 8
    for (int j = 0; j < 64; j++) {
        int y = yc + j;
        smf[o * SR + y] = fmaf(w0, xs[y], fmaf(w1, xs[256 + y], fmaf(w2v, xs[512 + y], bb)));
    }
    __syncthreads();

#pragma unroll
    for (int j = 0; j < 16; j++) {
        int slot = tid + j * 256;
        int oo = slot >> 6, y4 = (slot & 63) * 4;
        float4 v = *reinterpret_cast<const float4*>(&smf[oo * SR + y4]);
        *reinterpret_cast<float4*>(g_h0 + ((size_t)(b * 64 + oo) << 16) + xx * 256 + y4) = v;
    }
    fy_stage(smf, tbl, b, xx, tid);
}

// ---------------- stage 2a: x-forward DFT ----------------
__global__ __launch_bounds__(128) void dftx_fwd() {
    __shared__ float2 Fs[NN * MD];
    __shared__ float2 tb[NN];
    int t = threadIdx.x;
    int bc = blockIdx.x;
    const float4* src = reinterpret_cast<const float4*>(g_fy + (size_t)bc * NN * 32);
    float4* fd = reinterpret_cast<float4*>(Fs);
#pragma unroll
    for (int j = 0; j < 16; j++) fd[t + j * 128] = src[t + j * 128];
    tb[t] = g_tab[t];
    tb[t + 128] = g_tab[t + 128];
    __syncthreads();
    int k1 = t >> 3;
    int k2p = t & 7;
    float re0 = 0.f, im0 = 0.f, re1 = 0.f, im1 = 0.f;
    int m = 0;
#pragma unroll 8
    for (int x = 0; x < NN; x++) {
        float4 F = *reinterpret_cast<const float4*>(&Fs[x * 16 + k2p * 2]);
        float2 e = tb[m];
        m = (m + k1) & 255;
        re0 = fmaf(F.x, e.x, re0); re0 = fmaf(F.y, e.y, re0);
        im0 = fmaf(F.y, e.x, im0); im0 = fmaf(-F.x, e.y, im0);
        re1 = fmaf(F.z, e.x, re1); re1 = fmaf(F.w, e.y, re1);
        im1 = fmaf(F.w, e.x, im1); im1 = fmaf(-F.z, e.y, im1);
    }
    *reinterpret_cast<float4*>(g_fxy + (size_t)bc * 512 + k1 * 32 + k2p * 4) =
        make_float4(re0, im0, re1, im1);
}

// ---------------- stage 2b: per-mode channel mix (coalesced via swt) ----------------
__global__ __launch_bounds__(256) void mode_mix(int l) {
    __shared__ float WsR[WID * WID];
    __shared__ float WsI[WID * WID];
    __shared__ float2 Xs[BATCH * WID];
    int tid  = threadIdx.x;
    int mode = blockIdx.x;
    const float2* wsrc = reinterpret_cast<const float2*>(g_swt) +
                         (size_t)(l * 256 + mode) * 4096;
    for (int idx = tid; idx < WID * WID; idx += 256) {
        float2 v = wsrc[idx];
        WsR[idx] = v.x;
        WsI[idx] = v.y;
    }
    for (int idx = tid; idx < BATCH * WID; idx += 256) {
        const float* p = g_fxy + ((size_t)idx * 256 + mode) * 2;
        Xs[idx] = make_float2(p[0], p[1]);
    }
    __syncthreads();
    int o = tid & 63, bg = tid >> 6;
    const float sc = 1.0f / 65536.0f;
#pragma unroll
    for (int t = 0; t < 4; t++) {
        int b = bg * 4 + t;
        float aR = 0.f, aI = 0.f;
#pragma unroll 8
        for (int i = 0; i < 64; i++) {
            float2 X = Xs[b * 64 + i];
            float wr = WsR[i * 64 + o], wi = WsI[i * 64 + o];
            aR = fmaf(X.x, wr, aR); aR = fmaf(-X.y, wi, aR);
            aI = fmaf(X.x, wi, aI); aI = fmaf( X.y, wr, aI);
        }
        float* p = g_ymix + ((size_t)(b * 64 + o) * 256 + mode) * 2;
        p[0] = aR * sc;
        p[1] = aI * sc;
    }
}

// ---------------- stage 2c: x-inverse DFT ----------------
__global__ __launch_bounds__(256) void dftx_inv() {
    __shared__ float2 Ys[256];
    __shared__ float2 tb[NN];
    int tid = threadIdx.x;
    int bo  = blockIdx.x;
    Ys[tid] = reinterpret_cast<const float2*>(g_ymix)[(size_t)bo * 256 + tid];
    tb[tid] = g_tab[tid];
    __syncthreads();
    int x = tid;
    float2 acc[16];
#pragma unroll
    for (int k2 = 0; k2 < 16; k2++) acc[k2] = make_float2(0.f, 0.f);
    int m = 0;
#pragma unroll
    for (int k1 = 0; k1 < 16; k1++) {
        float2 e = tb[m];
        m = (m + x) & 255;
#pragma unroll
        for (int k2 = 0; k2 < 16; k2++) {
            float2 Yv = Ys[k1 * 16 + k2];
            acc[k2].x = fmaf(Yv.x, e.x, acc[k2].x); acc[k2].x = fmaf(-Yv.y, e.y, acc[k2].x);
            acc[k2].y = fmaf(Yv.x, e.y, acc[k2].y); acc[k2].y = fmaf( Yv.y, e.x, acc[k2].y);
        }
    }
    float* dst = g_gx + ((size_t)bo * 256 + x) * 32;
#pragma unroll
    for (int k2 = 0; k2 < 16; k2++) { dst[2 * k2] = acc[k2].x; dst[2 * k2 + 1] = acc[k2].y; }
}

// ---------------- stage 3 (mega-fused; radix-2 spectral fold + interleaved w/g) ----------------
// interleave slot for o = 8c+j: j<4 -> c*4+j, else 32 + c*4 + (j-4)   (per row, pitch 68)
#define OFF_CW  16384
#define OFF_TBL (OFF_CW + 4352)     // 20736, 2048 u64 = 4096 floats
#define OFF_GR  (OFF_TBL + 4096)    // 24832
#define OFF_GI  (OFF_GR + 1088)     // 25920
#define OFF_CB  (OFF_GI + 1088)     // 27008
#define OFF_HW  (OFF_CB + 64)
#define OFF_HB  (OFF_HW + 64)
#define CONV_FLOATS (OFF_HB + 8)
#define CONV_SMEM   (CONV_FLOATS * 4)

__global__ __launch_bounds__(256, 2) void conv_fused(int src, int dst,
                                                     const float* __restrict__ cw,
                                                     const float* __restrict__ cb,
                                                     int hasSpec, int doFy, int doHead,
                                                     const float* __restrict__ hw,
                                                     const float* __restrict__ hb,
                                                     float* __restrict__ out) {
    extern __shared__ float smf[];
    float* cws = smf + OFF_CW;
    u64*  tbl  = reinterpret_cast<u64*>(smf + OFF_TBL);
    float* gsRe = smf + OFF_GR;
    float* gsIm = smf + OFF_GI;
    float* cbs  = smf + OFF_CB;

    const float* __restrict__ hin = hbuf(src);
    float* __restrict__ hout = hbuf(dst);
    int tid = threadIdx.x;
    int b = blockIdx.x >> 8;
    int xx = blockIdx.x & 255;

    // ---- staging ----
    const float* hbase = hin + ((size_t)b * 64 * 256 + xx) * 256;
#pragma unroll
    for (int j = 0; j < 16; j++) {
        int slot = tid + j * 256;
        int i = slot >> 6, c4 = slot & 63;
        float4 v = *reinterpret_cast<const float4*>(hbase + (size_t)i * 65536 + c4 * 4);
        *reinterpret_cast<float4*>(&smf[i * 256 + c4 * 4]) = v;
    }
    for (int idx = tid; idx < 4096; idx += 256) {
        int o = idx >> 6, i = idx & 63;
        int c = o >> 3, j = o & 7;
        int slot = (j < 4) ? (c * 4 + j) : (32 + c * 4 + (j - 4));
        cws[i * 68 + slot] = cw[idx];
    }
    build_tbl(tbl, tid);
    if (hasSpec) {
        for (int idx = tid; idx < 1024; idx += 256) {
            int k2 = idx >> 6, o = idx & 63;
            int c = o >> 3, j = o & 7;
            int slot = (j < 4) ? (c * 4 + j) : (32 + c * 4 + (j - 4));
            const float* p = g_gx + (((size_t)(b * 64 + o) * 256 + xx) << 5) + 2 * k2;
            float d = (k2 > 0) ? 2.f : 1.f;
            gsRe[k2 * 68 + slot] = d * p[0];
            gsIm[k2 * 68 + slot] = d * p[1];
        }
    }
    if (tid < 64) cbs[tid] = cb[tid];
    if (doHead) {
        if (tid < 64) smf[OFF_HW + tid] = hw[tid];
        if (tid == 0) smf[OFF_HB] = hb[0];
    }
    __syncthreads();

    int cth = tid & 7;          // o-chunk: o0 = cth*8
    int y0  = (tid >> 3) * 4;   // low-half y base (0..124)

    // ---- spectral: even/odd k2 partial sums over low-half y ----
    u64 aE[4][4], aO[4][4];
#pragma unroll
    for (int a = 0; a < 4; a++)
#pragma unroll
        for (int c = 0; c < 4; c++) { aE[a][c] = 0ull; aO[a][c] = 0ull; }

    if (hasSpec) {
#pragma unroll
        for (int k2 = 0; k2 < 16; k2++) {
            int base = k2 * 68 + cth * 4;
            ulonglong2 rA = *reinterpret_cast<const ulonglong2*>(gsRe + base);
            ulonglong2 rB = *reinterpret_cast<const ulonglong2*>(gsRe + base + 32);
            ulonglong2 iA = *reinterpret_cast<const ulonglong2*>(gsIm + base);
            ulonglong2 iB = *reinterpret_cast<const ulonglong2*>(gsIm + base + 32);
            u64 gr[4] = {rA.x, rA.y, rB.x, rB.y};
            u64 gi[4] = {iA.x, iA.y, iB.x, iB.y};
            u64 (*T)[4] = (k2 & 1) ? aO : aE;
#pragma unroll
            for (int yy = 0; yy < 4; yy++) {
                float c, s; unpack2(tbl[(y0 + yy) * 16 + k2], c, s);   // (cos, -sin)
                u64 pc = pack2(c, c);
                u64 ps = pack2(s, s);
                ffma2(T[0][yy], gr[0], pc); ffma2(T[0][yy], gi[0], ps);
                ffma2(T[1][yy], gr[1], pc); ffma2(T[1][yy], gi[1], ps);
                ffma2(T[2][yy], gr[2], pc); ffma2(T[2][yy], gi[2], ps);
                ffma2(T[3][yy], gr[3], pc); ffma2(T[3][yy], gi[3], ps);
            }
        }
    }

    // combine: acc[op][0..3] = low-half y0..y0+3, acc[op][4..7] = high-half y0+128..
    const u64 NEG1 = pack2(-1.0f, -1.0f);
    u64 acc[4][8];
#pragma unroll
    for (int op = 0; op < 4; op++)
#pragma unroll
        for (int yy = 0; yy < 4; yy++) {
            u64 se = aE[op][yy], so = aO[op][yy];
            acc[op][yy]     = addf2(se, so);
            acc[op][yy + 4] = addf2(se, mulf2(so, NEG1));
        }

    // ---- conv1x1 mainloop ----
#pragma unroll 4
    for (int i = 0; i < 64; i++) {
        ulonglong2 wA = *reinterpret_cast<const ulonglong2*>(cws + i * 68 + cth * 4);
        ulonglong2 wB = *reinterpret_cast<const ulonglong2*>(cws + i * 68 + 32 + cth * 4);
        float4 hA = *reinterpret_cast<const float4*>(smf + i * 256 + y0);
        float4 hB = *reinterpret_cast<const float4*>(smf + i * 256 + 128 + y0);
        u64 w2[4] = {wA.x, wA.y, wB.x, wB.y};
        float hv[8] = {hA.x, hA.y, hA.z, hA.w, hB.x, hB.y, hB.z, hB.w};
#pragma unroll
        for (int yy = 0; yy < 8; yy++) {
            u64 h2 = pack2(hv[yy], hv[yy]);
            ffma2(acc[0][yy], w2[0], h2);
            ffma2(acc[1][yy], w2[1], h2);
            ffma2(acc[2][yy], w2[2], h2);
            ffma2(acc[3][yy], w2[3], h2);
        }
    }

    // ---- bias + exact GELU, writeback (low half at y0, high at y0+128) ----
    __syncthreads();
    int writeRes = doFy | doHead;
    int o0 = cth * 8;
#pragma unroll
    for (int oop = 0; oop < 4; oop++) {
        int oE = o0 + oop * 2, oO = oE + 1;
        float bE = cbs[oE], bO = cbs[oO];
        float vE[8], vO[8];
#pragma unroll
        for (int yy = 0; yy < 8; yy++) {
            float a, bb; unpack2(acc[oop][yy], a, bb);
            float v = a + bE;
            vE[yy] = 0.5f * v * (1.0f + erff(v * 0.70710678118654752f));
            float w = bb + bO;
            vO[yy] = 0.5f * w * (1.0f + erff(w * 0.70710678118654752f));
        }
        if (writeRes) {
            *reinterpret_cast<float4*>(&smf[oE * SR + y0      ]) = make_float4(vE[0], vE[1], vE[2], vE[3]);
            *reinterpret_cast<float4*>(&smf[oE * SR + y0 + 128]) = make_float4(vE[4], vE[5], vE[6], vE[7]);
            *reinterpret_cast<float4*>(&smf[oO * SR + y0      ]) = make_float4(vO[0], vO[1], vO[2], vO[3]);
            *reinterpret_cast<float4*>(&smf[oO * SR + y0 + 128]) = make_float4(vO[4], vO[5], vO[6], vO[7]);
        }
        if (!doHead) {
            float* dE = hout + ((size_t)(b * 64 + oE) << 16) + xx * 256;
            *reinterpret_cast<float4*>(dE + y0      ) = make_float4(vE[0], vE[1], vE[2], vE[3]);
            *reinterpret_cast<float4*>(dE + y0 + 128) = make_float4(vE[4], vE[5], vE[6], vE[7]);
            float* dO = hout + ((size_t)(b * 64 + oO) << 16) + xx * 256;
            *reinterpret_cast<float4*>(dO + y0      ) = make_float4(vO[0], vO[1], vO[2], vO[3]);
            *reinterpret_cast<float4*>(dO + y0 + 128) = make_float4(vO[4], vO[5], vO[6], vO[7]);
        }
    }

    if (doFy) {
        __syncthreads();
        fy_stage(smf, tbl, b, xx, tid);
    }
    if (doHead) {
        __syncthreads();
        const float* hwS = smf + OFF_HW;
        float a = smf[OFF_HB];
        int y = tid;
#pragma unroll 16
        for (int f = 0; f < 64; f++) a = fmaf(smf[f * SR + y], hwS[f], a);
        out[(size_t)b * 65536 + xx * 256 + y] = a;
    }
}

// ---------------- launch ----------------
extern "C" void kernel_launch(void* const* d_in, const int* in_sizes, int n_in,
                              void* d_out, int out_size) {
    const float* x     = (const float*)d_in[0];
    const float* fc0_w = (const float*)d_in[1];
    const float* fc0_b = (const float*)d_in[2];
    const float* sw[4] = {(const float*)d_in[3], (const float*)d_in[4],
                          (const float*)d_in[5], (const float*)d_in[6]};
    const float* cw[4] = {(const float*)d_in[7], (const float*)d_in[9],
                          (const float*)d_in[11], (const float*)d_in[13]};
    const float* cb[4] = {(const float*)d_in[8], (const float*)d_in[10],
                          (const float*)d_in[12], (const float*)d_in[14]};
    const float* fc1_w = (const float*)d_in[15];
    const float* fc1_b = (const float*)d_in[16];
    const float* fc2_w = (const float*)d_in[17];
    const float* fc2_b = (const float*)d_in[18];
    float* out = (float*)d_out;

    cudaFuncSetAttribute(conv_fused, cudaFuncAttributeMaxDynamicSharedMemorySize, CONV_SMEM);
    cudaFuncSetAttribute(fc0_fy,     cudaFuncAttributeMaxDynamicSharedMemorySize, F0_SMEM);

    init_tab_kernel<<<1, 256>>>();
    sw_transpose<<<2048, 256>>>(sw[0], sw[1], sw[2], sw[3]);
    fc0_fy<<<4096, 256, F0_SMEM>>>(x, fc0_w, fc0_b);

    int src = 0;
    for (int l = 0; l < 4; l++) {
        dftx_fwd<<<1024, 128>>>();
        mode_mix<<<256, 256>>>(l);
        dftx_inv<<<1024, 256>>>();
        int doFy = (l < 3) ? 1 : 0;
        conv_fused<<<4096, 256, CONV_SMEM>>>(src, 1 - src, cw[l], cb[l],
                                             1, doFy, 0, nullptr, nullptr, nullptr);
        src = 1 - src;
    }
    conv_fused<<<4096, 256, CONV_SMEM>>>(src, src, fc1_w, fc1_b,
                                         0, 0, 1, fc2_w, fc2_b, out);
}